// round 3
// baseline (speedup 1.0000x reference)
#include <cuda_runtime.h>

#define NQ 8
#define HD 256
#define S_TOT 8192
#define PAST 8191
#define HID 1536
#define INTER 6144
#define QDIM 2048
#define SCALE 0.0625f

// -------- scratch (device globals; no allocation allowed) --------
__device__ float g_qkv[2560];            // q[0:2048] (pre-scaled), k_new[2048:2304], v_new[2304:2560]
__device__ float g_scores[NQ * S_TOT];   // [h][s]
__device__ float g_stats[16];            // m[0:8], inv_l[8:16]
__device__ float g_attn[QDIM];           // attention output (atomic accum)
__device__ float g_h1[HID];              // post-attention residual
__device__ float g_mid[INTER];           // gelu(gate)*up

static __device__ __forceinline__ float4 f4add(float4 a, float4 b) {
    a.x += b.x; a.y += b.y; a.z += b.z; a.w += b.w; return a;
}
static __device__ __forceinline__ void f4fma(float4& a, float s, float4 w) {
    a.x += s * w.x; a.y += s * w.y; a.z += s * w.z; a.w += s * w.w;
}
static __device__ __forceinline__ float gelu_exact(float v) {
    return 0.5f * v * (1.0f + erff(v * 0.70710678118654752f));
}

// ============ K1: QKV projection (+bias, q pre-scaled by SCALE) ============
// 160 blocks x 256 thr. Block owns 16 output cols; C4=4, 64 rowgroups x 24 rows.
__global__ void k_qkv(const float* __restrict__ x,
                      const float* __restrict__ Wq, const float* __restrict__ bq,
                      const float* __restrict__ Wk, const float* __restrict__ bk,
                      const float* __restrict__ Wv, const float* __restrict__ bv) {
    __shared__ float4 sm[256];
    int t = threadIdx.x;
    int c4 = t & 3, rg = t >> 2;
    int colBase = blockIdx.x * 16;
    const float* W; const float* bias; int ld, wcol; float sc;
    if (colBase < 2048)      { W = Wq; bias = bq; ld = 2048; wcol = colBase;        sc = SCALE; }
    else if (colBase < 2304) { W = Wk; bias = bk; ld = 256;  wcol = colBase - 2048; sc = 1.0f; }
    else                     { W = Wv; bias = bv; ld = 256;  wcol = colBase - 2304; sc = 1.0f; }
    const float* wp = W + wcol + c4 * 4;
    float4 acc = make_float4(0.f, 0.f, 0.f, 0.f);
    int r0 = rg * 24;
#pragma unroll 8
    for (int i = 0; i < 24; i++) {
        int r = r0 + i;
        float xv = __ldg(x + r);
        float4 w = *(const float4*)(wp + (size_t)r * ld);
        f4fma(acc, xv, w);
    }
    sm[t] = acc;
    __syncthreads();
    for (int s = 128; s >= 4; s >>= 1) {
        if (t < s) sm[t] = f4add(sm[t], sm[t + s]);
        __syncthreads();
    }
    if (t < 4) {
        float4 a = sm[t];
        float4 b = *(const float4*)(bias + wcol + t * 4);
        a = f4add(a, b);
        a.x *= sc; a.y *= sc; a.z *= sc; a.w *= sc;
        *(float4*)&g_qkv[colBase + t * 4] = a;
    }
}

// ============ K2: scores[h][s] = q_h . K_s  (q already scaled) ============
// 128 blocks x 256 thr (8 warps). Warp handles 8 positions. q in registers.
__global__ void k_scores(const float* __restrict__ kp) {
    int t = threadIdx.x, lane = t & 31, wid = t >> 5;
    const float* q = g_qkv;
    float4 qa[8], qb[8];
#pragma unroll
    for (int h = 0; h < 8; h++) {
        qa[h] = *(const float4*)(q + h * 256 + lane * 8);
        qb[h] = *(const float4*)(q + h * 256 + lane * 8 + 4);
    }
    int gw = blockIdx.x * 8 + wid;   // 0..1023
#pragma unroll
    for (int it = 0; it < 8; it++) {
        int s = gw + it * 1024;
        const float* krow = (s < PAST) ? (kp + (size_t)s * 256) : (g_qkv + 2048);
        float4 ka = *(const float4*)(krow + lane * 8);
        float4 kb = *(const float4*)(krow + lane * 8 + 4);
        float acc[8];
#pragma unroll
        for (int h = 0; h < 8; h++) {
            acc[h] = qa[h].x * ka.x + qa[h].y * ka.y + qa[h].z * ka.z + qa[h].w * ka.w
                   + qb[h].x * kb.x + qb[h].y * kb.y + qb[h].z * kb.z + qb[h].w * kb.w;
        }
#pragma unroll
        for (int h = 0; h < 8; h++) {
#pragma unroll
            for (int off = 16; off; off >>= 1)
                acc[h] += __shfl_xor_sync(0xffffffffu, acc[h], off);
        }
#pragma unroll
        for (int h = 0; h < 8; h++)
            if (lane == h) g_scores[h * S_TOT + s] = acc[h];
    }
}

// ============ K3: per-head online softmax stats (m, 1/l); also zero g_attn ====
__global__ void k_stats() {
    __shared__ float sm_m[256], sm_l[256];
    int h = blockIdx.x, t = threadIdx.x;
    const float* sc = g_scores + h * S_TOT;
    float v[32];
#pragma unroll
    for (int i = 0; i < 8; i++) {
        float4 a = *(const float4*)(sc + t * 4 + i * 1024);
        v[i * 4 + 0] = a.x; v[i * 4 + 1] = a.y; v[i * 4 + 2] = a.z; v[i * 4 + 3] = a.w;
    }
    float m = -1e30f;
#pragma unroll
    for (int i = 0; i < 32; i++) m = fmaxf(m, v[i]);
    float l = 0.f;
#pragma unroll
    for (int i = 0; i < 32; i++) l += __expf(v[i] - m);
    sm_m[t] = m; sm_l[t] = l;
    __syncthreads();
    for (int s = 128; s >= 1; s >>= 1) {
        if (t < s) {
            float m1 = sm_m[t], l1 = sm_l[t];
            float m2 = sm_m[t + s], l2 = sm_l[t + s];
            float nm = fmaxf(m1, m2);
            sm_l[t] = l1 * __expf(m1 - nm) + l2 * __expf(m2 - nm);
            sm_m[t] = nm;
        }
        __syncthreads();
    }
    if (t == 0) { g_stats[h] = sm_m[0]; g_stats[8 + h] = 1.0f / sm_l[0]; }
    g_attn[h * 256 + t] = 0.0f;   // zero accumulator for K4 atomics
}

// ============ K4: out[h][d] += sum_s p[h][s] * V[s][d] ============
// 256 blocks x 256 thr. Block handles 32 positions; 4 groups of 64 threads over d.
__global__ void k_av(const float* __restrict__ vp) {
    __shared__ float  p_sm[32][8];
    __shared__ float4 red4[2048];   // [4 groups][8 heads][64 d4]
    int t = threadIdx.x;
    int sBase = blockIdx.x * 32;
    {
        int pos = t >> 3, h = t & 7;
        int s = sBase + pos;
        p_sm[pos][h] = __expf(g_scores[h * S_TOT + s] - g_stats[h]) * g_stats[8 + h];
    }
    __syncthreads();
    int g = t >> 6, l64 = t & 63;
    float4 acc[8];
#pragma unroll
    for (int h = 0; h < 8; h++) acc[h] = make_float4(0.f, 0.f, 0.f, 0.f);
#pragma unroll
    for (int j = 0; j < 8; j++) {
        int pos = g * 8 + j;
        int s = sBase + pos;
        const float* vrow = (s < PAST) ? (vp + (size_t)s * 256) : (g_qkv + 2304);
        float4 v = *(const float4*)(vrow + l64 * 4);
#pragma unroll
        for (int h = 0; h < 8; h++) f4fma(acc[h], p_sm[pos][h], v);
    }
#pragma unroll
    for (int h = 0; h < 8; h++) red4[g * 512 + h * 64 + l64] = acc[h];
    __syncthreads();
    float4* attn4 = (float4*)g_attn;
#pragma unroll
    for (int k = 0; k < 2; k++) {
        int o = t + 256 * k;   // 0..511 -> output floats [4o, 4o+4)
        float4 v = f4add(f4add(red4[o], red4[512 + o]), f4add(red4[1024 + o], red4[1536 + o]));
        atomicAdd(&attn4[o], v);   // sm_90+ vector RED
    }
}

// ============ K5: h1 = x + attn @ Wo + bo ============
// 192 blocks; block owns 8 cols; C4=2, 128 rowgroups x 16 rows (fan_in 2048).
__global__ void k_wo(const float* __restrict__ x,
                     const float* __restrict__ Wo, const float* __restrict__ bo) {
    __shared__ float4 sm[256];
    int t = threadIdx.x, c4 = t & 1, rg = t >> 1;
    int colBase = blockIdx.x * 8;
    const float* wp = Wo + colBase + c4 * 4;
    float4 acc = make_float4(0.f, 0.f, 0.f, 0.f);
    int r0 = rg * 16;
#pragma unroll 8
    for (int i = 0; i < 16; i++) {
        int r = r0 + i;
        float xv = g_attn[r];
        float4 w = *(const float4*)(wp + (size_t)r * 1536);
        f4fma(acc, xv, w);
    }
    sm[t] = acc;
    __syncthreads();
    for (int s = 128; s >= 2; s >>= 1) {
        if (t < s) sm[t] = f4add(sm[t], sm[t + s]);
        __syncthreads();
    }
    if (t < 2) {
        int col = colBase + t * 4;
        float4 a = f4add(sm[t], *(const float4*)(bo + col));
        a = f4add(a, *(const float4*)(x + col));
        *(float4*)&g_h1[col] = a;
    }
}

// ============ K6: mid = gelu(h1@Wg+bg) * (h1@Wu+bu) ============
// 192 blocks; block owns 32 cols of BOTH gate & up; C4=8, 32 rowgroups x 48 rows.
__global__ void k_gateup(const float* __restrict__ Wg, const float* __restrict__ bg,
                         const float* __restrict__ Wu, const float* __restrict__ bu) {
    __shared__ float4 smg[256], smu[256];
    int t = threadIdx.x, c4 = t & 7, rg = t >> 3;
    int colBase = blockIdx.x * 32;
    const float* wg = Wg + colBase + c4 * 4;
    const float* wu = Wu + colBase + c4 * 4;
    float4 ag = make_float4(0.f, 0.f, 0.f, 0.f);
    float4 au = make_float4(0.f, 0.f, 0.f, 0.f);
    int r0 = rg * 48;
#pragma unroll 4
    for (int i = 0; i < 48; i++) {
        int r = r0 + i;
        float xv = g_h1[r];
        float4 a = *(const float4*)(wg + (size_t)r * 6144);
        float4 b = *(const float4*)(wu + (size_t)r * 6144);
        f4fma(ag, xv, a);
        f4fma(au, xv, b);
    }
    smg[t] = ag; smu[t] = au;
    __syncthreads();
    for (int s = 128; s >= 8; s >>= 1) {
        if (t < s) { smg[t] = f4add(smg[t], smg[t + s]); smu[t] = f4add(smu[t], smu[t + s]); }
        __syncthreads();
    }
    if (t < 8) {
        int col = colBase + t * 4;
        float4 gv = f4add(smg[t], *(const float4*)(bg + col));
        float4 uv = f4add(smu[t], *(const float4*)(bu + col));
        float4 o;
        o.x = gelu_exact(gv.x) * uv.x;
        o.y = gelu_exact(gv.y) * uv.y;
        o.z = gelu_exact(gv.z) * uv.z;
        o.w = gelu_exact(gv.w) * uv.w;
        *(float4*)&g_mid[col] = o;
    }
}

// ============ K7: out = h1 + mid @ Wd + bd ============
// 192 blocks; block owns 8 cols; C4=2, 128 rowgroups x 48 rows (fan_in 6144).
__global__ void k_down(const float* __restrict__ Wd, const float* __restrict__ bd,
                       float* __restrict__ out) {
    __shared__ float4 sm[256];
    int t = threadIdx.x, c4 = t & 1, rg = t >> 1;
    int colBase = blockIdx.x * 8;
    const float* wp = Wd + colBase + c4 * 4;
    float4 acc = make_float4(0.f, 0.f, 0.f, 0.f);
    int r0 = rg * 48;
#pragma unroll 4
    for (int i = 0; i < 48; i++) {
        int r = r0 + i;
        float xv = g_mid[r];
        float4 w = *(const float4*)(wp + (size_t)r * 1536);
        f4fma(acc, xv, w);
    }
    sm[t] = acc;
    __syncthreads();
    for (int s = 128; s >= 2; s >>= 1) {
        if (t < s) sm[t] = f4add(sm[t], sm[t + s]);
        __syncthreads();
    }
    if (t < 2) {
        int col = colBase + t * 4;
        float4 a = f4add(sm[t], *(const float4*)(bd + col));
        a = f4add(a, *(const float4*)&g_h1[col]);
        *(float4*)&out[col] = a;
    }
}

extern "C" void kernel_launch(void* const* d_in, const int* in_sizes, int n_in,
                              void* d_out, int out_size) {
    const float* x  = (const float*)d_in[0];
    const float* kp = (const float*)d_in[1];
    const float* vp = (const float*)d_in[2];
    const float* Wq = (const float*)d_in[3];
    const float* bq = (const float*)d_in[4];
    const float* Wk = (const float*)d_in[5];
    const float* bk = (const float*)d_in[6];
    const float* Wv = (const float*)d_in[7];
    const float* bv = (const float*)d_in[8];
    const float* Wo = (const float*)d_in[9];
    const float* bo = (const float*)d_in[10];
    const float* Wg = (const float*)d_in[11];
    const float* bg = (const float*)d_in[12];
    const float* Wu = (const float*)d_in[13];
    const float* bu = (const float*)d_in[14];
    const float* Wd = (const float*)d_in[15];
    const float* bd = (const float*)d_in[16];

    k_qkv   <<<160, 256>>>(x, Wq, bq, Wk, bk, Wv, bv);
    k_scores<<<128, 256>>>(kp);
    k_stats <<<8,   256>>>();
    k_av    <<<256, 256>>>(vp);
    k_wo    <<<192, 256>>>(x, Wo, bo);
    k_gateup<<<192, 256>>>(Wg, bg, Wu, bu);
    k_down  <<<192, 256>>>(Wd, bd, (float*)d_out);
}

// round 4
// speedup vs baseline: 1.3348x; 1.3348x over previous
#include <cuda_runtime.h>

#define NQ 8
#define HD 256
#define S_TOT 8192
#define PAST 8191
#define HID 1536
#define INTER 6144
#define QDIM 2048
#define SCALE 0.0625f

// -------- scratch (device globals) --------
__device__ float g_qkv[2560];            // q[0:2048] (pre-scaled), k_new[2048:2304], v_new[2304:2560]
__device__ float g_scores[NQ * S_TOT];   // [h][s]
__device__ float g_part[128];            // per (head,slice) partial m [0:64], l [64:128]
__device__ float g_attn[QDIM];           // attention output (atomic accum)
__device__ float g_h1[HID];              // post-attention residual
__device__ float g_mid[INTER];           // gelu(gate)*up

static __device__ __forceinline__ float4 f4add(float4 a, float4 b) {
    a.x += b.x; a.y += b.y; a.z += b.z; a.w += b.w; return a;
}
static __device__ __forceinline__ void f4fma(float4& a, float s, float4 w) {
    a.x += s * w.x; a.y += s * w.y; a.z += s * w.z; a.w += s * w.w;
}
static __device__ __forceinline__ float gelu_exact(float v) {
    return 0.5f * v * (1.0f + erff(v * 0.70710678118654752f));
}

// Warp reduce preserving the low-lane "column" parity; after this, lanes
// 0..PMIN-1 hold the sums for their c4 slot.
template<int PMIN>
static __device__ __forceinline__ float4 wred(float4 v) {
#pragma unroll
    for (int off = 16; off >= PMIN; off >>= 1) {
        v.x += __shfl_xor_sync(0xffffffffu, v.x, off);
        v.y += __shfl_xor_sync(0xffffffffu, v.y, off);
        v.z += __shfl_xor_sync(0xffffffffu, v.z, off);
        v.w += __shfl_xor_sync(0xffffffffu, v.w, off);
    }
    return v;
}

// ============ K1: QKV projection (+bias, q pre-scaled by SCALE) ============
// 320 blocks x 512 thr. Block owns 8 output cols; c4 = t&1 (32B/row), 256 rowgroups x 6 rows.
__global__ __launch_bounds__(512) void k_qkv(
        const float* __restrict__ x,
        const float* __restrict__ Wq, const float* __restrict__ bq,
        const float* __restrict__ Wk, const float* __restrict__ bk,
        const float* __restrict__ Wv, const float* __restrict__ bv) {
    __shared__ float4 part[16 * 2];
    int t = threadIdx.x, lane = t & 31, wid = t >> 5;
    int c4 = t & 1, rg = t >> 1;
    int colBase = blockIdx.x * 8;
    const float* W; const float* bias; int ld, wcol; float sc;
    if (blockIdx.x < 256)      { W = Wq; bias = bq; ld = 2048; wcol = colBase;        sc = SCALE; }
    else if (blockIdx.x < 288) { W = Wk; bias = bk; ld = 256;  wcol = colBase - 2048; sc = 1.0f; }
    else                       { W = Wv; bias = bv; ld = 256;  wcol = colBase - 2304; sc = 1.0f; }
    const float* wp = W + wcol + c4 * 4;
    float4 acc = make_float4(0.f, 0.f, 0.f, 0.f);
    int r0 = rg * 6;
#pragma unroll
    for (int i = 0; i < 6; i++) {
        int r = r0 + i;
        float xv = __ldg(x + r);
        float4 w = *(const float4*)(wp + (size_t)r * ld);
        f4fma(acc, xv, w);
    }
    acc = wred<2>(acc);
    if (lane < 2) part[wid * 2 + lane] = acc;
    __syncthreads();
    if (t < 2) {
        float4 s = part[t];
#pragma unroll
        for (int w = 1; w < 16; w++) s = f4add(s, part[w * 2 + t]);
        int col = wcol + t * 4;
        float4 b = *(const float4*)(bias + col);
        s = f4add(s, b);
        s.x *= sc; s.y *= sc; s.z *= sc; s.w *= sc;
        *(float4*)&g_qkv[colBase + t * 4] = s;
    }
}

// ============ K2: scores[h][s] = q_h . K_s  (q already scaled) ============
// 512 blocks x 256 thr (8 warps). Warp handles 2 positions (s, s+4096).
__global__ __launch_bounds__(256) void k_scores(const float* __restrict__ kp) {
    int t = threadIdx.x, lane = t & 31, wid = t >> 5;
    const float* q = g_qkv;
    float4 qa[8], qb[8];
#pragma unroll
    for (int h = 0; h < 8; h++) {
        qa[h] = *(const float4*)(q + h * 256 + lane * 8);
        qb[h] = *(const float4*)(q + h * 256 + lane * 8 + 4);
    }
    int gw = blockIdx.x * 8 + wid;          // 0..4095
    int s0 = gw, s1 = gw + 4096;
    const float* kr0 = (s0 < PAST) ? (kp + (size_t)s0 * 256) : (g_qkv + 2048);
    const float* kr1 = (s1 < PAST) ? (kp + (size_t)s1 * 256) : (g_qkv + 2048);
    float4 ka0 = *(const float4*)(kr0 + lane * 8);
    float4 kb0 = *(const float4*)(kr0 + lane * 8 + 4);
    float4 ka1 = *(const float4*)(kr1 + lane * 8);
    float4 kb1 = *(const float4*)(kr1 + lane * 8 + 4);
#pragma unroll
    for (int it = 0; it < 2; it++) {
        float4 ka = it ? ka1 : ka0;
        float4 kb = it ? kb1 : kb0;
        int s = it ? s1 : s0;
        float acc[8];
#pragma unroll
        for (int h = 0; h < 8; h++) {
            acc[h] = qa[h].x * ka.x + qa[h].y * ka.y + qa[h].z * ka.z + qa[h].w * ka.w
                   + qb[h].x * kb.x + qb[h].y * kb.y + qb[h].z * kb.z + qb[h].w * kb.w;
        }
#pragma unroll
        for (int h = 0; h < 8; h++) {
#pragma unroll
            for (int off = 16; off; off >>= 1)
                acc[h] += __shfl_xor_sync(0xffffffffu, acc[h], off);
        }
#pragma unroll
        for (int h = 0; h < 8; h++)
            if (lane == h) g_scores[h * S_TOT + s] = acc[h];
    }
}

// ============ K3: partial softmax stats per (head, slice of 1024); zero g_attn ====
// 64 blocks x 256 thr. Block bb: head = bb>>3, slice = bb&7.
__global__ __launch_bounds__(256) void k_stats() {
    __shared__ float sm_m[256], sm_l[256];
    int bb = blockIdx.x, t = threadIdx.x;
    int h = bb >> 3, sl = bb & 7;
    const float* sc = g_scores + h * S_TOT + sl * 1024;
    float4 a = *(const float4*)(sc + t * 4);
    float m = fmaxf(fmaxf(a.x, a.y), fmaxf(a.z, a.w));
    float l = __expf(a.x - m) + __expf(a.y - m) + __expf(a.z - m) + __expf(a.w - m);
    sm_m[t] = m; sm_l[t] = l;
    __syncthreads();
    for (int s = 128; s >= 1; s >>= 1) {
        if (t < s) {
            float m1 = sm_m[t], l1 = sm_l[t];
            float m2 = sm_m[t + s], l2 = sm_l[t + s];
            float nm = fmaxf(m1, m2);
            sm_l[t] = l1 * __expf(m1 - nm) + l2 * __expf(m2 - nm);
            sm_m[t] = nm;
        }
        __syncthreads();
    }
    if (t == 0) { g_part[bb] = sm_m[0]; g_part[64 + bb] = sm_l[0]; }
    if (bb < 8) g_attn[bb * 256 + t] = 0.0f;   // zero accumulator for K4 atomics
}

// ============ K4: out[h][d] += sum_s p[h][s] * V[s][d] ============
// 512 blocks x 256 thr. Block handles 16 positions. Thread owns (head-pair, d4),
// accumulates over all 16 positions (V rows read 4x, 3 from L1). No big smem.
__global__ __launch_bounds__(256) void k_av(const float* __restrict__ vp) {
    __shared__ float p_sm[16][8];
    __shared__ float s_m[8], s_il[8];
    int t = threadIdx.x;
    int sBase = blockIdx.x * 16;
    if (t < 8) {
        float m = g_part[t * 8], l = g_part[64 + t * 8];
#pragma unroll
        for (int i = 1; i < 8; i++) {
            float m2 = g_part[t * 8 + i], l2 = g_part[64 + t * 8 + i];
            float nm = fmaxf(m, m2);
            l = l * __expf(m - nm) + l2 * __expf(m2 - nm);
            m = nm;
        }
        s_m[t] = m; s_il[t] = 1.0f / l;
    }
    __syncthreads();
    if (t < 128) {
        int pos = t >> 3, h = t & 7;
        p_sm[pos][h] = __expf(g_scores[h * S_TOT + sBase + pos] - s_m[h]) * s_il[h];
    }
    __syncthreads();
    int d4 = t & 63, hp = t >> 6;            // 4 head-pairs
    int h0 = hp * 2, h1 = h0 + 1;
    float4 acc0 = make_float4(0.f, 0.f, 0.f, 0.f);
    float4 acc1 = make_float4(0.f, 0.f, 0.f, 0.f);
#pragma unroll
    for (int j = 0; j < 16; j++) {
        int s = sBase + j;
        const float* vrow = (s < PAST) ? (vp + (size_t)s * 256) : (g_qkv + 2304);
        float4 v = *(const float4*)(vrow + d4 * 4);
        f4fma(acc0, p_sm[j][h0], v);
        f4fma(acc1, p_sm[j][h1], v);
    }
    float4* attn4 = (float4*)g_attn;
    atomicAdd(&attn4[h0 * 64 + d4], acc0);
    atomicAdd(&attn4[h1 * 64 + d4], acc1);
}

// ============ K5: h1 = x + attn @ Wo + bo ============
// 192 blocks x 512 thr. Block owns 8 cols; c4 = t&1, 256 rowgroups x 8 rows (fan_in 2048).
__global__ __launch_bounds__(512) void k_wo(
        const float* __restrict__ x,
        const float* __restrict__ Wo, const float* __restrict__ bo) {
    __shared__ float4 part[16 * 2];
    int t = threadIdx.x, lane = t & 31, wid = t >> 5;
    int c4 = t & 1, rg = t >> 1;
    int colBase = blockIdx.x * 8;
    const float* wp = Wo + colBase + c4 * 4;
    float4 acc = make_float4(0.f, 0.f, 0.f, 0.f);
    int r0 = rg * 8;
#pragma unroll
    for (int i = 0; i < 8; i++) {
        int r = r0 + i;
        float xv = g_attn[r];
        float4 w = *(const float4*)(wp + (size_t)r * 1536);
        f4fma(acc, xv, w);
    }
    acc = wred<2>(acc);
    if (lane < 2) part[wid * 2 + lane] = acc;
    __syncthreads();
    if (t < 2) {
        float4 s = part[t];
#pragma unroll
        for (int w = 1; w < 16; w++) s = f4add(s, part[w * 2 + t]);
        int col = colBase + t * 4;
        s = f4add(s, *(const float4*)(bo + col));
        s = f4add(s, *(const float4*)(x + col));
        *(float4*)&g_h1[col] = s;
    }
}

// ============ K6: mid = gelu(h1@Wg+bg) * (h1@Wu+bu) ============
// 384 blocks x 512 thr. Block owns 16 cols of both; c4 = t&3 (64B/row), 128 rowgroups x 12 rows.
__global__ __launch_bounds__(512) void k_gateup(
        const float* __restrict__ Wg, const float* __restrict__ bg,
        const float* __restrict__ Wu, const float* __restrict__ bu) {
    __shared__ float4 pg[16 * 4], pu[16 * 4];
    int t = threadIdx.x, lane = t & 31, wid = t >> 5;
    int c4 = t & 3, rg = t >> 2;
    int colBase = blockIdx.x * 16;
    const float* wg = Wg + colBase + c4 * 4;
    const float* wu = Wu + colBase + c4 * 4;
    float4 ag = make_float4(0.f, 0.f, 0.f, 0.f);
    float4 au = make_float4(0.f, 0.f, 0.f, 0.f);
    int r0 = rg * 12;
#pragma unroll
    for (int i = 0; i < 12; i++) {
        int r = r0 + i;
        float xv = g_h1[r];
        float4 a = *(const float4*)(wg + (size_t)r * 6144);
        float4 b = *(const float4*)(wu + (size_t)r * 6144);
        f4fma(ag, xv, a);
        f4fma(au, xv, b);
    }
    ag = wred<4>(ag);
    au = wred<4>(au);
    if (lane < 4) { pg[wid * 4 + lane] = ag; pu[wid * 4 + lane] = au; }
    __syncthreads();
    if (t < 4) {
        float4 sg = pg[t], su = pu[t];
#pragma unroll
        for (int w = 1; w < 16; w++) { sg = f4add(sg, pg[w * 4 + t]); su = f4add(su, pu[w * 4 + t]); }
        int col = colBase + t * 4;
        float4 gv = f4add(sg, *(const float4*)(bg + col));
        float4 uv = f4add(su, *(const float4*)(bu + col));
        float4 o;
        o.x = gelu_exact(gv.x) * uv.x;
        o.y = gelu_exact(gv.y) * uv.y;
        o.z = gelu_exact(gv.z) * uv.z;
        o.w = gelu_exact(gv.w) * uv.w;
        *(float4*)&g_mid[col] = o;
    }
}

// ============ K7: out = h1 + mid @ Wd + bd ============
// 192 blocks x 512 thr. Block owns 8 cols; c4 = t&1, 256 rowgroups x 24 rows (fan_in 6144).
__global__ __launch_bounds__(512) void k_down(
        const float* __restrict__ Wd, const float* __restrict__ bd,
        float* __restrict__ out) {
    __shared__ float4 part[16 * 2];
    int t = threadIdx.x, lane = t & 31, wid = t >> 5;
    int c4 = t & 1, rg = t >> 1;
    int colBase = blockIdx.x * 8;
    const float* wp = Wd + colBase + c4 * 4;
    float4 acc = make_float4(0.f, 0.f, 0.f, 0.f);
    int r0 = rg * 24;
#pragma unroll 12
    for (int i = 0; i < 24; i++) {
        int r = r0 + i;
        float xv = g_mid[r];
        float4 w = *(const float4*)(wp + (size_t)r * 1536);
        f4fma(acc, xv, w);
    }
    acc = wred<2>(acc);
    if (lane < 2) part[wid * 2 + lane] = acc;
    __syncthreads();
    if (t < 2) {
        float4 s = part[t];
#pragma unroll
        for (int w = 1; w < 16; w++) s = f4add(s, part[w * 2 + t]);
        int col = colBase + t * 4;
        s = f4add(s, *(const float4*)(bd + col));
        s = f4add(s, *(const float4*)&g_h1[col]);
        *(float4*)&out[col] = s;
    }
}

extern "C" void kernel_launch(void* const* d_in, const int* in_sizes, int n_in,
                              void* d_out, int out_size) {
    const float* x  = (const float*)d_in[0];
    const float* kp = (const float*)d_in[1];
    const float* vp = (const float*)d_in[2];
    const float* Wq = (const float*)d_in[3];
    const float* bq = (const float*)d_in[4];
    const float* Wk = (const float*)d_in[5];
    const float* bk = (const float*)d_in[6];
    const float* Wv = (const float*)d_in[7];
    const float* bv = (const float*)d_in[8];
    const float* Wo = (const float*)d_in[9];
    const float* bo = (const float*)d_in[10];
    const float* Wg = (const float*)d_in[11];
    const float* bg = (const float*)d_in[12];
    const float* Wu = (const float*)d_in[13];
    const float* bu = (const float*)d_in[14];
    const float* Wd = (const float*)d_in[15];
    const float* bd = (const float*)d_in[16];

    k_qkv   <<<320, 512>>>(x, Wq, bq, Wk, bk, Wv, bv);
    k_scores<<<512, 256>>>(kp);
    k_stats <<<64,  256>>>();
    k_av    <<<512, 256>>>(vp);
    k_wo    <<<192, 512>>>(x, Wo, bo);
    k_gateup<<<384, 512>>>(Wg, bg, Wu, bu);
    k_down  <<<192, 512>>>(Wd, bd, (float*)d_out);
}